// round 7
// baseline (speedup 1.0000x reference)
#include <cuda_runtime.h>
#include <cuda_bf16.h>
#include <mma.h>

using namespace nvcuda;

#define NN 100000
#define NE 3200000
#define CH 128

// Scratch (static device globals: allocation-free per harness rules)
__device__ int   g_is64;                  // 1 if edge_index is int64, 0 if int32
__device__ int   g_cnt[NN];               // in-degree (excl. self loop)
__device__ int   g_off[NN];               // CSR offsets (exclusive scan of cnt)
__device__ int   g_cur[NN];               // scatter cursors
__device__ int   g_csr[NE];               // source ids grouped by target
__device__ float g_dinv[NN];
__device__ float g_xw[(size_t)NN * CH];   // X @ W (unscaled), 51.2 MB (L2-resident)

// ---------------------------------------------------------------------------
// Dtype probe: int64 indices have all-zero high words; int32 pairs do not.
// ---------------------------------------------------------------------------
__global__ void k_detect(const int2* __restrict__ ei) {
    if (threadIdx.x == 0 && blockIdx.x == 0) {
        int any_hi = 0;
#pragma unroll 8
        for (int i = 0; i < 256; i++) any_hi |= ei[i].y;
        g_is64 = (any_hi == 0) ? 1 : 0;
    }
}

__device__ __forceinline__ int edge_at(const void* __restrict__ ei, long long pos) {
    if (g_is64) return (int)((const long long*)ei)[pos];
    return ((const int*)ei)[pos];
}

// ---------------------------------------------------------------------------
// CSR build: count -> scan(+dinv) -> scatter
// ---------------------------------------------------------------------------
__global__ void k_zero_cnt() {
    int i = blockIdx.x * blockDim.x + threadIdx.x;
    if (i < NN) g_cnt[i] = 0;
}

__global__ void k_count(const void* __restrict__ ei) {
    int e = blockIdx.x * blockDim.x + threadIdx.x;
    if (e < NE) atomicAdd(&g_cnt[edge_at(ei, (long long)NE + e)], 1);
}

// Single-block exclusive scan of g_cnt -> g_off/g_cur; also computes g_dinv.
__global__ void __launch_bounds__(1024) k_scan() {
    __shared__ int warp_sums[32];
    const int t    = threadIdx.x;
    const int per  = (NN + 1023) / 1024;              // 98
    const int lane = t & 31, wid = t >> 5;
    int start = t * per;
    int end   = start + per; if (end > NN) end = NN;
    if (start > NN) start = NN;

    int s = 0;
    for (int i = start; i < end; i++) s += g_cnt[i];

    int v = s;
#pragma unroll
    for (int o = 1; o < 32; o <<= 1) {
        int u = __shfl_up_sync(0xFFFFFFFFu, v, o);
        if (lane >= o) v += u;
    }
    if (lane == 31) warp_sums[wid] = v;
    __syncthreads();
    if (wid == 0) {
        int w = warp_sums[lane];
#pragma unroll
        for (int o = 1; o < 32; o <<= 1) {
            int u = __shfl_up_sync(0xFFFFFFFFu, w, o);
            if (lane >= o) w += u;
        }
        warp_sums[lane] = w;
    }
    __syncthreads();

    int run = v - s + (wid > 0 ? warp_sums[wid - 1] : 0);
    for (int i = start; i < end; i++) {
        int c = g_cnt[i];
        g_off[i]  = run;
        g_cur[i]  = run;
        g_dinv[i] = rsqrtf(1.0f + (float)c);
        run += c;
    }
}

__global__ void k_scatter(const void* __restrict__ ei) {
    int e = blockIdx.x * blockDim.x + threadIdx.x;
    if (e < NE) {
        int r = edge_at(ei, e);                     // source
        int c = edge_at(ei, (long long)NE + e);     // target
        int pos = atomicAdd(&g_cur[c], 1);
        g_csr[pos] = r;
    }
}

// ---------------------------------------------------------------------------
// Tensor-core GEMM (tf32): g_xw = X @ W, fp32 accumulate.
// Block = 8 warps x 16 rows = 128 rows; each warp: 16 rows x all 128 cols
// (8 accumulator fragments). 100000 % 16 == 0, so row tiles are always full.
// ---------------------------------------------------------------------------
__global__ void __launch_bounds__(256) k_gemm_tc(const float* __restrict__ X,
                                                 const float* __restrict__ W) {
    const int wid  = threadIdx.x >> 5;
    const int row0 = blockIdx.x * 128 + wid * 16;
    if (row0 >= NN) return;

    wmma::fragment<wmma::accumulator, 16, 16, 8, float> c[8];
#pragma unroll
    for (int n = 0; n < 8; n++) wmma::fill_fragment(c[n], 0.0f);

    wmma::fragment<wmma::matrix_a, 16, 16, 8, wmma::precision::tf32, wmma::row_major> a;
    wmma::fragment<wmma::matrix_b, 16, 16, 8, wmma::precision::tf32, wmma::row_major> b;

    for (int k = 0; k < CH; k += 8) {
        wmma::load_matrix_sync(a, X + (size_t)row0 * CH + k, CH);
#pragma unroll
        for (int i = 0; i < a.num_elements; i++)
            a.x[i] = wmma::__float_to_tf32(a.x[i]);
#pragma unroll
        for (int n = 0; n < 8; n++) {
            wmma::load_matrix_sync(b, W + (size_t)k * CH + n * 16, CH);
#pragma unroll
            for (int i = 0; i < b.num_elements; i++)
                b.x[i] = wmma::__float_to_tf32(b.x[i]);
            wmma::mma_sync(c[n], a, b, c[n]);
        }
    }

#pragma unroll
    for (int n = 0; n < 8; n++)
        wmma::store_matrix_sync(&g_xw[(size_t)row0 * CH + n * 16], c[n], CH,
                                wmma::mem_row_major);
}

// ---------------------------------------------------------------------------
// Pull-mode aggregation: one warp per target node, zero atomics.
//   out[c] = dinv[c] * (dinv[c]*xw[c] + sum_{r} dinv[r]*xw[r]) + bias
// ---------------------------------------------------------------------------
__global__ void __launch_bounds__(256) k_aggr(float* __restrict__ out,
                                              const float* __restrict__ bias) {
    int warp = (blockIdx.x * 256 + threadIdx.x) >> 5;
    int lane = threadIdx.x & 31;
    if (warp >= NN) return;
    const int c   = warp;
    const int off = g_off[c];
    const int n   = g_cnt[c];
    const float sc = g_dinv[c];

    // self-loop term
    float4 vc = *(const float4*)&g_xw[(size_t)c * CH + lane * 4];
    float4 acc = make_float4(sc * vc.x, sc * vc.y, sc * vc.z, sc * vc.w);

    for (int i = 0; i < n; i += 32) {
        int chunk = n - i; if (chunk > 32) chunk = 32;
        int   r  = 0;
        float dr = 0.0f;
        if (lane < chunk) {
            r  = __ldg(&g_csr[off + i + lane]);
            dr = __ldg(&g_dinv[r]);
        }
#pragma unroll 4
        for (int j = 0; j < chunk; j++) {
            int   rj = __shfl_sync(0xFFFFFFFFu, r, j);
            float sj = __shfl_sync(0xFFFFFFFFu, dr, j);
            float4 v = *(const float4*)&g_xw[(size_t)rj * CH + lane * 4];
            acc.x += sj * v.x; acc.y += sj * v.y;
            acc.z += sj * v.z; acc.w += sj * v.w;
        }
    }

    float4 b = *(const float4*)&bias[lane * 4];
    float4 o = make_float4(sc * acc.x + b.x, sc * acc.y + b.y,
                           sc * acc.z + b.z, sc * acc.w + b.w);
    *(float4*)&out[(size_t)c * CH + lane * 4] = o;
}

// ---------------------------------------------------------------------------
extern "C" void kernel_launch(void* const* d_in, const int* in_sizes, int n_in,
                              void* d_out, int out_size) {
    const float* X    = (const float*)d_in[0];
    const void*  ei   = d_in[1];                 // [2, NE], int32 OR int64
    // d_in[2] = batch (unused by GCNConv)
    const float* W    = (const float*)d_in[3];
    const float* bias = (const float*)d_in[4];
    float*       out  = (float*)d_out;

    k_detect<<<1, 32>>>((const int2*)ei);

    // CSR build
    k_zero_cnt<<<(NN + 255) / 256, 256>>>();
    k_count<<<(NE + 255) / 256, 256>>>(ei);
    k_scan<<<1, 1024>>>();
    k_scatter<<<(NE + 255) / 256, 256>>>(ei);

    // xw = X @ W (tf32 tensor cores)
    k_gemm_tc<<<(NN + 127) / 128, 256>>>(X, W);

    // pull-mode aggregate (warp per node)
    k_aggr<<<(NN * 32 + 255) / 256, 256>>>(out, bias);
}

// round 8
// speedup vs baseline: 1.7713x; 1.7713x over previous
#include <cuda_runtime.h>
#include <cuda_bf16.h>
#include <mma.h>

using namespace nvcuda;

#define NN 100000
#define NE 3200000
#define CH 128
#define NB ((NN + 255) / 256)   // 391 scan blocks

// Scratch (static device globals: allocation-free per harness rules)
__device__ int   g_is64;                  // 1 if edge_index is int64, 0 if int32
__device__ int   g_cnt[NN];               // in-degree (excl. self loop)
__device__ int   g_off[NN];               // CSR offsets (exclusive scan of cnt)
__device__ int   g_cur[NN];               // scatter cursors
__device__ int   g_csr[NE];               // source ids grouped by target
__device__ int   g_bsum[NB];              // per-block count sums
__device__ int   g_bpre[NB];              // exclusive prefix of block sums
__device__ float g_dinv[NN];
__device__ float g_xw[(size_t)NN * CH];   // X @ W (unscaled), 51.2 MB (L2-resident)

// ---------------------------------------------------------------------------
// Dtype probe: int64 indices have all-zero high words; int32 pairs do not.
// ---------------------------------------------------------------------------
__global__ void k_detect(const int2* __restrict__ ei) {
    if (threadIdx.x == 0 && blockIdx.x == 0) {
        int any_hi = 0;
#pragma unroll 8
        for (int i = 0; i < 256; i++) any_hi |= ei[i].y;
        g_is64 = (any_hi == 0) ? 1 : 0;
    }
}

__device__ __forceinline__ int edge_at(const void* __restrict__ ei, long long pos) {
    if (g_is64) return (int)((const long long*)ei)[pos];
    return ((const int*)ei)[pos];
}

// ---------------------------------------------------------------------------
// CSR build: count -> 2-level parallel scan -> scatter
// ---------------------------------------------------------------------------
__global__ void k_zero_cnt() {
    int i = blockIdx.x * blockDim.x + threadIdx.x;
    if (i < NN) g_cnt[i] = 0;
}

__global__ void k_count(const void* __restrict__ ei) {
    int e = blockIdx.x * blockDim.x + threadIdx.x;
    if (e < NE) atomicAdd(&g_cnt[edge_at(ei, (long long)NE + e)], 1);
}

// Level 1: per-block sum of 256 counts.
__global__ void __launch_bounds__(256) k_blocksum() {
    __shared__ int wsum[8];
    int i    = blockIdx.x * 256 + threadIdx.x;
    int lane = threadIdx.x & 31, wid = threadIdx.x >> 5;
    int v = (i < NN) ? g_cnt[i] : 0;
#pragma unroll
    for (int o = 16; o > 0; o >>= 1) v += __shfl_down_sync(0xFFFFFFFFu, v, o);
    if (lane == 0) wsum[wid] = v;
    __syncthreads();
    if (wid == 0) {
        int s = (lane < 8) ? wsum[lane] : 0;
#pragma unroll
        for (int o = 4; o > 0; o >>= 1) s += __shfl_down_sync(0xFFFFFFFFu, s, o);
        if (lane == 0) g_bsum[blockIdx.x] = s;
    }
}

// Level 2: single block scans NB (=391) block sums -> exclusive prefixes.
__global__ void __launch_bounds__(512) k_scanb() {
    __shared__ int sh[512];
    int t = threadIdx.x;
    int v = (t < NB) ? g_bsum[t] : 0;
    sh[t] = v;
    __syncthreads();
    for (int o = 1; o < 512; o <<= 1) {
        int u = (t >= o) ? sh[t - o] : 0;
        __syncthreads();
        sh[t] += u;
        __syncthreads();
    }
    if (t < NB) g_bpre[t] = sh[t] - v;   // exclusive
}

// Level 3: intra-block exclusive scan + block prefix -> off/cur/dinv.
__global__ void __launch_bounds__(256) k_fill() {
    __shared__ int wpre[8];
    int i    = blockIdx.x * 256 + threadIdx.x;
    int lane = threadIdx.x & 31, wid = threadIdx.x >> 5;
    int c = (i < NN) ? g_cnt[i] : 0;

    // inclusive warp scan
    int v = c;
#pragma unroll
    for (int o = 1; o < 32; o <<= 1) {
        int u = __shfl_up_sync(0xFFFFFFFFu, v, o);
        if (lane >= o) v += u;
    }
    if (lane == 31) wpre[wid] = v;
    __syncthreads();
    if (wid == 0 && lane < 8) {
        int w = wpre[lane];
#pragma unroll
        for (int o = 1; o < 8; o <<= 1) {
            int u = __shfl_up_sync(0x000000FFu, w, o);
            if (lane >= o) w += u;
        }
        wpre[lane] = w;
    }
    __syncthreads();

    if (i < NN) {
        int excl = v - c + (wid > 0 ? wpre[wid - 1] : 0) + g_bpre[blockIdx.x];
        g_off[i]  = excl;
        g_cur[i]  = excl;
        g_dinv[i] = rsqrtf(1.0f + (float)c);
    }
}

__global__ void k_scatter(const void* __restrict__ ei) {
    int e = blockIdx.x * blockDim.x + threadIdx.x;
    if (e < NE) {
        int r = edge_at(ei, e);                     // source
        int c = edge_at(ei, (long long)NE + e);     // target
        int pos = atomicAdd(&g_cur[c], 1);
        g_csr[pos] = r;
    }
}

// ---------------------------------------------------------------------------
// Tensor-core GEMM (tf32): g_xw = X @ W, fp32 accumulate.
// Block = 8 warps x 16 rows = 128 rows; each warp: 16 rows x all 128 cols.
// ---------------------------------------------------------------------------
__global__ void __launch_bounds__(256) k_gemm_tc(const float* __restrict__ X,
                                                 const float* __restrict__ W) {
    const int wid  = threadIdx.x >> 5;
    const int row0 = blockIdx.x * 128 + wid * 16;
    if (row0 >= NN) return;

    wmma::fragment<wmma::accumulator, 16, 16, 8, float> c[8];
#pragma unroll
    for (int n = 0; n < 8; n++) wmma::fill_fragment(c[n], 0.0f);

    wmma::fragment<wmma::matrix_a, 16, 16, 8, wmma::precision::tf32, wmma::row_major> a;
    wmma::fragment<wmma::matrix_b, 16, 16, 8, wmma::precision::tf32, wmma::row_major> b;

    for (int k = 0; k < CH; k += 8) {
        wmma::load_matrix_sync(a, X + (size_t)row0 * CH + k, CH);
#pragma unroll
        for (int i = 0; i < a.num_elements; i++)
            a.x[i] = wmma::__float_to_tf32(a.x[i]);
#pragma unroll
        for (int n = 0; n < 8; n++) {
            wmma::load_matrix_sync(b, W + (size_t)k * CH + n * 16, CH);
#pragma unroll
            for (int i = 0; i < b.num_elements; i++)
                b.x[i] = wmma::__float_to_tf32(b.x[i]);
            wmma::mma_sync(c[n], a, b, c[n]);
        }
    }

#pragma unroll
    for (int n = 0; n < 8; n++)
        wmma::store_matrix_sync(&g_xw[(size_t)row0 * CH + n * 16], c[n], CH,
                                wmma::mem_row_major);
}

// ---------------------------------------------------------------------------
// Pull-mode aggregation: one warp per target node, zero atomics.
//   out[c] = dinv[c] * (dinv[c]*xw[c] + sum_{r} dinv[r]*xw[r]) + bias
// ---------------------------------------------------------------------------
__global__ void __launch_bounds__(256) k_aggr(float* __restrict__ out,
                                              const float* __restrict__ bias) {
    int warp = (blockIdx.x * 256 + threadIdx.x) >> 5;
    int lane = threadIdx.x & 31;
    if (warp >= NN) return;
    const int c   = warp;
    const int off = g_off[c];
    const int n   = g_cnt[c];
    const float sc = g_dinv[c];

    // self-loop term
    float4 vc = *(const float4*)&g_xw[(size_t)c * CH + lane * 4];
    float4 acc = make_float4(sc * vc.x, sc * vc.y, sc * vc.z, sc * vc.w);

    for (int i = 0; i < n; i += 32) {
        int chunk = n - i; if (chunk > 32) chunk = 32;
        int   r  = 0;
        float dr = 0.0f;
        if (lane < chunk) {
            r  = __ldg(&g_csr[off + i + lane]);
            dr = __ldg(&g_dinv[r]);
        }
#pragma unroll 4
        for (int j = 0; j < chunk; j++) {
            int   rj = __shfl_sync(0xFFFFFFFFu, r, j);
            float sj = __shfl_sync(0xFFFFFFFFu, dr, j);
            float4 v = *(const float4*)&g_xw[(size_t)rj * CH + lane * 4];
            acc.x += sj * v.x; acc.y += sj * v.y;
            acc.z += sj * v.z; acc.w += sj * v.w;
        }
    }

    float4 b = *(const float4*)&bias[lane * 4];
    float4 o = make_float4(sc * acc.x + b.x, sc * acc.y + b.y,
                           sc * acc.z + b.z, sc * acc.w + b.w);
    *(float4*)&out[(size_t)c * CH + lane * 4] = o;
}

// ---------------------------------------------------------------------------
extern "C" void kernel_launch(void* const* d_in, const int* in_sizes, int n_in,
                              void* d_out, int out_size) {
    const float* X    = (const float*)d_in[0];
    const void*  ei   = d_in[1];                 // [2, NE], int32 OR int64
    // d_in[2] = batch (unused by GCNConv)
    const float* W    = (const float*)d_in[3];
    const float* bias = (const float*)d_in[4];
    float*       out  = (float*)d_out;

    k_detect<<<1, 32>>>((const int2*)ei);

    // CSR build with 2-level parallel scan
    k_zero_cnt<<<NB, 256>>>();
    k_count<<<(NE + 255) / 256, 256>>>(ei);
    k_blocksum<<<NB, 256>>>();
    k_scanb<<<1, 512>>>();
    k_fill<<<NB, 256>>>();
    k_scatter<<<(NE + 255) / 256, 256>>>(ei);

    // xw = X @ W (tf32 tensor cores)
    k_gemm_tc<<<(NN + 127) / 128, 256>>>(X, W);

    // pull-mode aggregate (warp per node)
    k_aggr<<<(NN * 32 + 255) / 256, 256>>>(out, bias);
}